// round 1
// baseline (speedup 1.0000x reference)
#include <cuda_runtime.h>
#include <math.h>

#define N_   16384
#define L_   15
#define K_   64
#define H_   16
#define NY_  15
#define S_   2048
#define NEG  (-1e30f)
#define SEG_ 128          // number of DP segments
#define SEGLEN_ (N_/SEG_) // 128

// ---------------- scratch (device globals; no allocation allowed) ------------
__device__ float g_WT[2][64*64];      // transposed+permuted Wih per dir
__device__ float g_biasP[2][64];      // permuted bih+bhh
__device__ float g_proj[2][(size_t)N_*64];   // permuted input projections
__device__ float g_h[2][(size_t)L_*N_*H_];   // fwd/bwd hidden states [l][n][h]
__device__ float g_A[N_*16];          // A[p][d], stride 16 (d=15 unused)
__device__ float g_gtab[15*15];       // scores[p][p][y] for p<15
__device__ float g_ypart[15*16];      // Y_enc @ V2^T
__device__ float g_zb[15*16];         // Z_enc @ V3^T + V_b
__device__ float g_M[SEG_*15*16];     // per-segment transfer rows [seg][i][j]

// ---------------- fast math helpers -----------------------------------------
__device__ __forceinline__ float sigm(float x) {
    return __fdividef(1.0f, 1.0f + __expf(-x));
}
__device__ __forceinline__ float ftanh(float x) {
    return __fdividef(2.0f, 1.0f + __expf(-2.0f*x)) - 1.0f;
}
__device__ __forceinline__ float max15(const float x[15]) {
    float a = fmaxf(x[0],x[1]),  b = fmaxf(x[2],x[3]);
    float c = fmaxf(x[4],x[5]),  d = fmaxf(x[6],x[7]);
    float e = fmaxf(x[8],x[9]),  f = fmaxf(x[10],x[11]);
    float g = fmaxf(x[12],x[13]);
    a = fmaxf(a,b); c = fmaxf(c,d); e = fmaxf(e,f); g = fmaxf(g,x[14]);
    a = fmaxf(a,c); e = fmaxf(e,g);
    return fmaxf(a,e);
}
__device__ __forceinline__ float lse15(const float x[15]) {
    float m = max15(x);
    float s0 = __expf(x[0]-m)  + __expf(x[1]-m);
    float s1 = __expf(x[2]-m)  + __expf(x[3]-m);
    float s2 = __expf(x[4]-m)  + __expf(x[5]-m);
    float s3 = __expf(x[6]-m)  + __expf(x[7]-m);
    float s4 = __expf(x[8]-m)  + __expf(x[9]-m);
    float s5 = __expf(x[10]-m) + __expf(x[11]-m);
    float s6 = __expf(x[12]-m) + __expf(x[13]-m);
    float s7 = __expf(x[14]-m);
    s0 += s1; s2 += s3; s4 += s5; s6 += s7;
    s0 += s2; s4 += s6;
    return m + __logf(s0 + s4);
}

// ---------------- K0: tiny prep ---------------------------------------------
__global__ void k_prep(const float* __restrict__ fWih, const float* __restrict__ fbih,
                       const float* __restrict__ fbhh, const float* __restrict__ bWih,
                       const float* __restrict__ bbih, const float* __restrict__ bbhh,
                       const float* __restrict__ Yenc, const float* __restrict__ Zenc,
                       const float* __restrict__ VW,   const float* __restrict__ Vb) {
    int t = threadIdx.x;
    // transposed, gate-permuted Wih:   g_WT[dir][k*64 + (j*4+c)] = Wih[c*16+j][k]
    for (int i = t; i < 4096; i += 256) {
        int k = i >> 6, m = i & 63, j = m >> 2, c = m & 3, r = c*16 + j;
        g_WT[0][k*64 + m] = fWih[r*64 + k];
        g_WT[1][k*64 + m] = bWih[r*64 + k];
    }
    if (t < 64) {
        int j = t >> 2, c = t & 3, r = c*16 + j;
        g_biasP[0][t] = fbih[r] + fbhh[r];
        g_biasP[1][t] = bbih[r] + bbhh[r];
    }
    if (t < 240) {
        int y = t >> 4, h = t & 15;
        float s = 0.0f;
        for (int u = 0; u < 32; u++) s += Yenc[y*32 + u] * VW[h*68 + 32 + u];
        g_ypart[t] = s;
        float z = Vb[h];
        for (int u = 0; u < 4; u++) z += Zenc[y*4 + u] * VW[h*68 + 64 + u];
        g_zb[t] = z;
    }
}

// ---------------- K1: input projection (2 small GEMMs) -----------------------
__global__ void __launch_bounds__(128) k_proj(const float* __restrict__ data) {
    const int dir = blockIdx.y;
    __shared__ float WTs[4096];
    __shared__ float bs[64];
    for (int i = threadIdx.x; i < 4096; i += 128) WTs[i] = g_WT[dir][i];
    if (threadIdx.x < 64) bs[threadIdx.x] = g_biasP[dir][threadIdx.x];
    __syncthreads();

    int n = blockIdx.x * 128 + threadIdx.x;
    float d[64];
    const float4* dp = (const float4*)(data + (size_t)n * 64);
#pragma unroll
    for (int i = 0; i < 16; i++) {
        float4 v = dp[i];
        d[i*4+0] = v.x; d[i*4+1] = v.y; d[i*4+2] = v.z; d[i*4+3] = v.w;
    }
    float4* outp = (float4*)(g_proj[dir] + (size_t)n * 64);
    const float4* W4 = (const float4*)WTs;
    for (int mf = 0; mf < 16; mf++) {
        float4 acc = make_float4(bs[mf*4+0], bs[mf*4+1], bs[mf*4+2], bs[mf*4+3]);
#pragma unroll
        for (int k = 0; k < 64; k++) {
            float4 w = W4[k*16 + mf];
            acc.x += d[k]*w.x; acc.y += d[k]*w.y; acc.z += d[k]*w.z; acc.w += d[k]*w.w;
        }
        outp[mf] = acc;
    }
}

// ---------------- K2: 32768 independent 15-step LSTMs -------------------------
// 16 lanes per run (lane j owns hidden unit j), 2 runs per warp.
__global__ void __launch_bounds__(256) k_lstm(const float* __restrict__ fWhh,
                                              const float* __restrict__ bWhh,
                                              const float* __restrict__ fh0,
                                              const float* __restrict__ fc0,
                                              const float* __restrict__ bh0,
                                              const float* __restrict__ bc0) {
    const int dir = blockIdx.y;
    __shared__ float Ws[1024];
    __shared__ float h0s[16], c0s[16];
    const float* Whh = dir ? bWhh : fWhh;
    for (int i = threadIdx.x; i < 1024; i += 256) Ws[i] = Whh[i];
    if (threadIdx.x < 16) {
        h0s[threadIdx.x] = dir ? bh0[threadIdx.x] : fh0[threadIdx.x];
        c0s[threadIdx.x] = dir ? bc0[threadIdx.x] : fc0[threadIdx.x];
    }
    __syncthreads();

    int lane = threadIdx.x & 31;
    int j = lane & 15;
    int gw = blockIdx.x * 8 + (threadIdx.x >> 5);
    int n = gw * 2 + (lane >> 4);

    float wi[16], wf[16], wg[16], wo[16];
#pragma unroll
    for (int k = 0; k < 16; k++) {
        wi[k] = Ws[(0  + j)*16 + k];
        wf[k] = Ws[(16 + j)*16 + k];
        wg[k] = Ws[(32 + j)*16 + k];
        wo[k] = Ws[(48 + j)*16 + k];
    }
    float h[16];
#pragma unroll
    for (int k = 0; k < 16; k++) h[k] = h0s[k];
    float c = c0s[j];

    const float* proj = g_proj[dir];
    float* out = g_h[dir];

    for (int l = 0; l < 15; l++) {
        int idx = dir ? max(n - l, 0) : min(n + l, N_ - 1);
        float4 p4 = *(const float4*)(proj + (size_t)idx * 64 + j * 4);
        float ai = p4.x, af = p4.y, ag = p4.z, ao = p4.w;
#pragma unroll
        for (int k = 0; k < 16; k++) {
            ai += h[k]*wi[k]; af += h[k]*wf[k]; ag += h[k]*wg[k]; ao += h[k]*wo[k];
        }
        float tg = ftanh(ag);
        c = sigm(af)*c + sigm(ai)*tg;
        float hj = sigm(ao)*ftanh(c);
        out[((size_t)l*N_ + n)*16 + j] = hj;
#pragma unroll
        for (int k = 0; k < 16; k++) h[k] = __shfl_sync(0xffffffffu, hj, k, 16);
    }
}

// ---------------- K3: scores + logsumexp over y -> A[p][d] --------------------
__global__ void __launch_bounds__(256) k_scores(const float* __restrict__ VW,
                                                const float* __restrict__ WW,
                                                const float* __restrict__ Wb) {
    __shared__ float V1S[512];   // [h][32]
    __shared__ float ypS[240];   // [y][16]
    __shared__ float zbS[240];   // [d][16]
    __shared__ float Wsh[16];
    __shared__ float Wbs;
    int t = threadIdx.y * 16 + threadIdx.x;
    for (int i = t; i < 512; i += 256) {
        int h = i >> 5, k = i & 31;
        V1S[i] = VW[h*68 + k];
    }
    if (t < 240) { ypS[t] = g_ypart[t]; zbS[t] = g_zb[t]; }
    if (t < 16)  Wsh[t] = WW[t];
    if (t == 0)  Wbs = Wb[0];
    __syncthreads();

    int d = threadIdx.x;
    int p = blockIdx.x * 16 + threadIdx.y;
    if (d >= 15) return;
    int pm = max(p - d, 0);

    float fg[16], bw[16];
    const float4* f4 = (const float4*)(g_h[0] + ((size_t)d*N_ + pm)*16);
    const float4* b4 = (const float4*)(g_h[1] + ((size_t)d*N_ + p )*16);
#pragma unroll
    for (int i = 0; i < 4; i++) {
        float4 v = f4[i];
        fg[i*4+0]=v.x; fg[i*4+1]=v.y; fg[i*4+2]=v.z; fg[i*4+3]=v.w;
        float4 u = b4[i];
        bw[i*4+0]=u.x; bw[i*4+1]=u.y; bw[i*4+2]=u.z; bw[i*4+3]=u.w;
    }
    float bse[16];
#pragma unroll
    for (int h = 0; h < 16; h++) {
        float acc = zbS[d*16 + h];
#pragma unroll
        for (int k = 0; k < 16; k++) acc += fg[k] * V1S[h*32 + k];
#pragma unroll
        for (int k = 0; k < 16; k++) acc += bw[k] * V1S[h*32 + 16 + k];
        bse[h] = acc;
    }
    float sarr[15];
#pragma unroll
    for (int y = 0; y < 15; y++) {
        float s = Wbs;
#pragma unroll
        for (int h = 0; h < 16; h++) s += Wsh[h] * ftanh(bse[h] + ypS[y*16 + h]);
        sarr[y] = s;
    }
    float A = lse15(sarr);
    if (d > p) A = NEG;
    g_A[p*16 + d] = A;
    if (p < 15 && d == p) {
#pragma unroll
        for (int y = 0; y < 15; y++) g_gtab[p*15 + y] = sarr[y];
    }
}

// ---------------- K4a: per-segment DP transfer matrices ----------------------
// lane j owns column j; ring[k] = coefficient of incoming hist[k].
__global__ void __launch_bounds__(128) k_dp1() {
    int lane = threadIdx.x & 31;
    int j = lane & 15;
    int seg = (blockIdx.x * 4 + (threadIdx.x >> 5)) * 2 + (lane >> 4);

    float ring[15];
#pragma unroll
    for (int k = 0; k < 15; k++) ring[k] = (j == k) ? 0.0f : NEG;

    int base = seg * SEGLEN_;
    for (int t = 0; t < SEGLEN_; t++) {
        float myA = g_A[(size_t)(base + t) * 16 + j];
        float x[15];
#pragma unroll
        for (int k = 0; k < 15; k++)
            x[k] = __shfl_sync(0xffffffffu, myA, k, 16) + ring[k];
        float nw = lse15(x);
#pragma unroll
        for (int k = 14; k > 0; k--) ring[k] = ring[k-1];
        ring[0] = nw;
    }
    if (j < 15) {
#pragma unroll
        for (int i = 0; i < 15; i++)
            g_M[((size_t)seg*15 + i)*16 + j] = ring[i];
    }
}

// ---------------- K4b: serial combine + indiv + output ------------------------
__global__ void __launch_bounds__(256) k_final(const int* __restrict__ tags,
                                               const int* __restrict__ lens,
                                               float* __restrict__ out) {
    __shared__ float s_logZ;
    __shared__ float parts[256];
    int tid = threadIdx.x;

    if (tid < 32) {
        int i = tid & 15;
        int ic = min(i, 14);
        float v = (i == 0) ? 0.0f : NEG;
        for (int g = 0; g < SEG_; g++) {
            const float* Mr = g_M + ((size_t)g*15 + ic)*16;
            float x[15];
#pragma unroll
            for (int k = 0; k < 15; k++)
                x[k] = Mr[k] + __shfl_sync(0xffffffffu, v, k, 16);
            v = lse15(x);
        }
        if (tid == 0) s_logZ = v;
    }
    float part = 0.0f;
    for (int s = tid; s < S_; s += 256) {
        int l = lens[s];
        if (l < 15) part += g_gtab[(l-1)*15 + tags[s]];
    }
    parts[tid] = part;
    __syncthreads();
    if (tid == 0) {
        float ind = 0.0f;
        for (int i = 0; i < 256; i++) ind += parts[i];
        out[0] = s_logZ - ind;
    }
}

// ---------------- launch ------------------------------------------------------
extern "C" void kernel_launch(void* const* d_in, const int* in_sizes, int n_in,
                              void* d_out, int out_size) {
    const float* data   = (const float*)d_in[0];
    const float* fWih   = (const float*)d_in[1];
    const float* fWhh   = (const float*)d_in[2];
    const float* fbih   = (const float*)d_in[3];
    const float* fbhh   = (const float*)d_in[4];
    const float* bWih   = (const float*)d_in[5];
    const float* bWhh   = (const float*)d_in[6];
    const float* bbih   = (const float*)d_in[7];
    const float* bbhh   = (const float*)d_in[8];
    const float* fh0    = (const float*)d_in[9];
    const float* fc0    = (const float*)d_in[10];
    const float* bh0    = (const float*)d_in[11];
    const float* bc0    = (const float*)d_in[12];
    const float* Yenc   = (const float*)d_in[13];
    const float* Zenc   = (const float*)d_in[14];
    const float* VW     = (const float*)d_in[15];
    const float* Vb     = (const float*)d_in[16];
    const float* WW     = (const float*)d_in[17];
    const float* Wb     = (const float*)d_in[18];
    const int*   tags   = (const int*)d_in[19];
    const int*   lens   = (const int*)d_in[20];
    float* out = (float*)d_out;

    k_prep<<<1, 256>>>(fWih, fbih, fbhh, bWih, bbih, bbhh, Yenc, Zenc, VW, Vb);
    k_proj<<<dim3(N_/128, 2), 128>>>(data);
    k_lstm<<<dim3(N_/16, 2), 256>>>(fWhh, bWhh, fh0, fc0, bh0, bc0);
    k_scores<<<N_/16, dim3(16, 16)>>>(VW, WW, Wb);
    k_dp1<<<SEG_/8, 128>>>();
    k_final<<<1, 256>>>(tags, lens, out);
}

// round 2
// speedup vs baseline: 1.5851x; 1.5851x over previous
#include <cuda_runtime.h>
#include <math.h>

#define N_   16384
#define L_   15
#define K_   64
#define H_   16
#define NY_  15
#define S_   2048
#define NEG  (-1e30f)
#define SEG_ 256          // number of DP segments
#define SEGLEN_ (N_/SEG_) // 64
#define GRP_ 16           // groups after dp2
#define PERG_ (SEG_/GRP_) // 16

typedef unsigned long long u64;

// ---------------- scratch (device globals; no allocation allowed) ------------
__device__ float g_proj[2][(size_t)N_*64];   // permuted input projections
__device__ float g_h[2][(size_t)L_*N_*H_];   // fwd/bwd hidden states [l][n][h]
__device__ float g_A[N_*16];                 // A[p][d], stride 16 (d=15 unused)
__device__ float g_gtab[15*15];              // scores[p][p][y] for p<15
__device__ float g_M[SEG_*15*16];            // per-segment transfer rows [seg][i][j]
__device__ float g_M2[GRP_*15*16];           // combined matrices

// ---------------- fast math helpers -----------------------------------------
__device__ __forceinline__ float tanh_ap(float x) {
    float y; asm("tanh.approx.f32 %0, %1;" : "=f"(y) : "f"(x)); return y;
}
__device__ __forceinline__ float sigm(float x) {
    return fmaf(tanh_ap(0.5f*x), 0.5f, 0.5f);
}
__device__ __forceinline__ u64 pk2(float lo, float hi) {
    u64 r; asm("mov.b64 %0, {%1,%2};" : "=l"(r) : "f"(lo), "f"(hi)); return r;
}
__device__ __forceinline__ u64 fma2(u64 a, u64 b, u64 c) {
    u64 d; asm("fma.rn.f32x2 %0, %1, %2, %3;" : "=l"(d) : "l"(a), "l"(b), "l"(c)); return d;
}
__device__ __forceinline__ float2 upk2(u64 a) {
    float lo, hi; asm("mov.b64 {%0,%1}, %2;" : "=f"(lo), "=f"(hi) : "l"(a));
    float2 v; v.x = lo; v.y = hi; return v;
}
__device__ __forceinline__ float max15(const float x[15]) {
    float a = fmaxf(x[0],x[1]),  b = fmaxf(x[2],x[3]);
    float c = fmaxf(x[4],x[5]),  d = fmaxf(x[6],x[7]);
    float e = fmaxf(x[8],x[9]),  f = fmaxf(x[10],x[11]);
    float g = fmaxf(x[12],x[13]);
    a = fmaxf(a,b); c = fmaxf(c,d); e = fmaxf(e,f); g = fmaxf(g,x[14]);
    a = fmaxf(a,c); e = fmaxf(e,g);
    return fmaxf(a,e);
}
__device__ __forceinline__ float lse15(const float x[15]) {
    float m = max15(x);
    float s0 = __expf(x[0]-m)  + __expf(x[1]-m);
    float s1 = __expf(x[2]-m)  + __expf(x[3]-m);
    float s2 = __expf(x[4]-m)  + __expf(x[5]-m);
    float s3 = __expf(x[6]-m)  + __expf(x[7]-m);
    float s4 = __expf(x[8]-m)  + __expf(x[9]-m);
    float s5 = __expf(x[10]-m) + __expf(x[11]-m);
    float s6 = __expf(x[12]-m) + __expf(x[13]-m);
    float s7 = __expf(x[14]-m);
    s0 += s1; s2 += s3; s4 += s5; s6 += s7;
    s0 += s2; s4 += s6;
    return m + __logf(s0 + s4);
}

// ---------------- K1: input projection (2 small GEMMs) -----------------------
__global__ void __launch_bounds__(128) k_proj(const float* __restrict__ data,
                                              const float* __restrict__ fWih,
                                              const float* __restrict__ bWih,
                                              const float* __restrict__ fbih,
                                              const float* __restrict__ fbhh,
                                              const float* __restrict__ bbih,
                                              const float* __restrict__ bbhh) {
    const int dir = blockIdx.y;
    const float* Wih = dir ? bWih : fWih;
    const float* bih = dir ? bbih : fbih;
    const float* bhh = dir ? bbhh : fbhh;
    __shared__ __align__(16) float WTs[4096];
    __shared__ float bs[64];
    // transposed, gate-permuted Wih: WTs[k*64 + (j*4+c)] = Wih[(c*16+j)*64 + k]
    for (int i = threadIdx.x; i < 4096; i += 128) {
        int k = i >> 6, m = i & 63, j = m >> 2, c = m & 3, r = c*16 + j;
        WTs[i] = Wih[r*64 + k];
    }
    if (threadIdx.x < 64) {
        int j = threadIdx.x >> 2, c = threadIdx.x & 3, r = c*16 + j;
        bs[threadIdx.x] = bih[r] + bhh[r];
    }
    __syncthreads();

    int n = blockIdx.x * 128 + threadIdx.x;
    float d[64];
    const float4* dp = (const float4*)(data + (size_t)n * 64);
#pragma unroll
    for (int i = 0; i < 16; i++) {
        float4 v = dp[i];
        d[i*4+0] = v.x; d[i*4+1] = v.y; d[i*4+2] = v.z; d[i*4+3] = v.w;
    }
    float4* outp = (float4*)(g_proj[dir] + (size_t)n * 64);
    const float4* W4 = (const float4*)WTs;
    for (int mf = 0; mf < 16; mf++) {
        float4 acc = make_float4(bs[mf*4+0], bs[mf*4+1], bs[mf*4+2], bs[mf*4+3]);
#pragma unroll
        for (int k = 0; k < 64; k++) {
            float4 w = W4[k*16 + mf];
            acc.x += d[k]*w.x; acc.y += d[k]*w.y; acc.z += d[k]*w.z; acc.w += d[k]*w.w;
        }
        outp[mf] = acc;
    }
}

// ---------------- K2: 32768 independent 15-step LSTMs -------------------------
// 16 lanes per run (lane j owns hidden unit j), 2 runs per warp.
__global__ void __launch_bounds__(256) k_lstm(const float* __restrict__ fWhh,
                                              const float* __restrict__ bWhh,
                                              const float* __restrict__ fh0,
                                              const float* __restrict__ fc0,
                                              const float* __restrict__ bh0,
                                              const float* __restrict__ bc0) {
    const int dir = blockIdx.y;
    __shared__ __align__(16) float Ws[1024];
    __shared__ float h0s[16], c0s[16];
    const float* Whh = dir ? bWhh : fWhh;
    for (int i = threadIdx.x; i < 1024; i += 256) Ws[i] = Whh[i];
    if (threadIdx.x < 16) {
        h0s[threadIdx.x] = dir ? bh0[threadIdx.x] : fh0[threadIdx.x];
        c0s[threadIdx.x] = dir ? bc0[threadIdx.x] : fc0[threadIdx.x];
    }
    __syncthreads();

    int lane = threadIdx.x & 31;
    int j = lane & 15;
    int gw = blockIdx.x * 8 + (threadIdx.x >> 5);
    int n = gw * 2 + (lane >> 4);

    u64 wi2[8], wf2[8], wg2[8], wo2[8];
#pragma unroll
    for (int k = 0; k < 8; k++) {
        wi2[k] = *(const u64*)&Ws[(0  + j)*16 + 2*k];
        wf2[k] = *(const u64*)&Ws[(16 + j)*16 + 2*k];
        wg2[k] = *(const u64*)&Ws[(32 + j)*16 + 2*k];
        wo2[k] = *(const u64*)&Ws[(48 + j)*16 + 2*k];
    }
    float h[16];
#pragma unroll
    for (int k = 0; k < 16; k++) h[k] = h0s[k];
    float c = c0s[j];

    const float* proj = g_proj[dir];
    float* out = g_h[dir];

    for (int l = 0; l < 15; l++) {
        int idx = dir ? max(n - l, 0) : min(n + l, N_ - 1);
        float4 p4 = *(const float4*)(proj + (size_t)idx * 64 + j * 4);
        u64 h2[8];
#pragma unroll
        for (int k = 0; k < 8; k++) h2[k] = pk2(h[2*k], h[2*k+1]);
        u64 ai2 = pk2(p4.x, 0.f), af2 = pk2(p4.y, 0.f);
        u64 ag2 = pk2(p4.z, 0.f), ao2 = pk2(p4.w, 0.f);
#pragma unroll
        for (int k = 0; k < 8; k++) {
            ai2 = fma2(h2[k], wi2[k], ai2);
            af2 = fma2(h2[k], wf2[k], af2);
            ag2 = fma2(h2[k], wg2[k], ag2);
            ao2 = fma2(h2[k], wo2[k], ao2);
        }
        float2 vi = upk2(ai2), vf = upk2(af2), vg = upk2(ag2), vo = upk2(ao2);
        float ai = vi.x + vi.y, af = vf.x + vf.y;
        float ag = vg.x + vg.y, ao = vo.x + vo.y;
        float tg = tanh_ap(ag);
        c = sigm(af)*c + sigm(ai)*tg;
        float hj = sigm(ao)*tanh_ap(c);
        out[((size_t)l*N_ + n)*16 + j] = hj;
#pragma unroll
        for (int k = 0; k < 16; k++) h[k] = __shfl_sync(0xffffffffu, hj, k, 16);
    }
}

// ---------------- K3: scores + logsumexp over y -> A[p][d] --------------------
__global__ void __launch_bounds__(256) k_scores(const float* __restrict__ Yenc,
                                                const float* __restrict__ Zenc,
                                                const float* __restrict__ VW,
                                                const float* __restrict__ Vb,
                                                const float* __restrict__ WW,
                                                const float* __restrict__ Wb) {
    __shared__ __align__(16) float V1S[512];   // [h][32]
    __shared__ __align__(8)  float ypS[240];   // [y][16]
    __shared__ __align__(8)  float zbS[240];   // [d][16]
    __shared__ float Wsh[16];
    __shared__ float Wbs;
    int t = threadIdx.y * 16 + threadIdx.x;
    for (int i = t; i < 512; i += 256) {
        int h = i >> 5, k = i & 31;
        V1S[i] = VW[h*68 + k];
    }
    if (t < 240) {
        int y = t >> 4, h = t & 15;
        float s = 0.0f;
        for (int u = 0; u < 32; u++) s += Yenc[y*32 + u] * VW[h*68 + 32 + u];
        ypS[t] = s;
        float z = Vb[h];
        for (int u = 0; u < 4; u++) z += Zenc[y*4 + u] * VW[h*68 + 64 + u];
        zbS[t] = z;
    }
    if (t < 16)  Wsh[t] = WW[t];
    if (t == 0)  Wbs = Wb[0];
    __syncthreads();

    int d = threadIdx.x;
    int p = blockIdx.x * 16 + threadIdx.y;
    if (d >= 15) return;
    int pm = max(p - d, 0);

    u64 fg2[8], bw2[8];
    const ulonglong2* f4 = (const ulonglong2*)(g_h[0] + ((size_t)d*N_ + pm)*16);
    const ulonglong2* b4 = (const ulonglong2*)(g_h[1] + ((size_t)d*N_ + p )*16);
#pragma unroll
    for (int i = 0; i < 4; i++) {
        ulonglong2 v = f4[i]; fg2[2*i] = v.x; fg2[2*i+1] = v.y;
        ulonglong2 u = b4[i]; bw2[2*i] = u.x; bw2[2*i+1] = u.y;
    }
    float bse[16];
#pragma unroll
    for (int h = 0; h < 16; h++) {
        u64 acc = pk2(zbS[d*16 + h], 0.0f);
#pragma unroll
        for (int k = 0; k < 8; k++)
            acc = fma2(fg2[k], *(const u64*)&V1S[h*32 + 2*k], acc);
#pragma unroll
        for (int k = 0; k < 8; k++)
            acc = fma2(bw2[k], *(const u64*)&V1S[h*32 + 16 + 2*k], acc);
        float2 a = upk2(acc);
        bse[h] = a.x + a.y;
    }
    float sarr[15];
#pragma unroll
    for (int y = 0; y < 15; y++) {
        float s = Wbs;
#pragma unroll
        for (int h = 0; h < 16; h++)
            s = fmaf(Wsh[h], tanh_ap(bse[h] + ypS[y*16 + h]), s);
        sarr[y] = s;
    }
    float A = lse15(sarr);
    if (d > p) A = NEG;
    g_A[p*16 + d] = A;
    if (p < 15 && d == p) {
#pragma unroll
        for (int y = 0; y < 15; y++) g_gtab[p*15 + y] = sarr[y];
    }
}

// ---------------- K4a: per-segment DP transfer matrices ----------------------
// lane j owns column j; ring[k] = coefficient of incoming hist[k].
__global__ void __launch_bounds__(256) k_dp1() {
    int lane = threadIdx.x & 31;
    int j = lane & 15;
    int seg = (blockIdx.x * 8 + (threadIdx.x >> 5)) * 2 + (lane >> 4);

    float ring[15];
#pragma unroll
    for (int k = 0; k < 15; k++) ring[k] = (j == k) ? 0.0f : NEG;

    int base = seg * SEGLEN_;
#pragma unroll 2
    for (int t = 0; t < SEGLEN_; t++) {
        float myA = g_A[(size_t)(base + t) * 16 + j];
        float x[15];
#pragma unroll
        for (int k = 0; k < 15; k++)
            x[k] = __shfl_sync(0xffffffffu, myA, k, 16) + ring[k];
        float nw = lse15(x);
#pragma unroll
        for (int k = 14; k > 0; k--) ring[k] = ring[k-1];
        ring[0] = nw;
    }
    if (j < 15) {
#pragma unroll
        for (int i = 0; i < 15; i++)
            g_M[((size_t)seg*15 + i)*16 + j] = ring[i];
    }
}

// ---------------- K4b: parallel 16:1 matrix combine ---------------------------
// block g combines matrices [16g .. 16g+15] into g_M2[g].
// lane i (0..15 within half-warp) holds P[i][j] for column j = warp*2+half.
__global__ void __launch_bounds__(256) k_dp2() {
    int lane = threadIdx.x & 31;
    int i = lane & 15;
    int ic = min(i, 14);
    int j = (threadIdx.x >> 5) * 2 + (lane >> 4);   // 0..15
    int g = blockIdx.x;
    int m0 = g * PERG_;

    float P = g_M[((size_t)m0*15 + ic)*16 + j];
#pragma unroll
    for (int tt = 1; tt < PERG_; tt++) {
        const float4* Mr = (const float4*)(g_M + ((size_t)(m0+tt)*15 + ic)*16);
        float4 r0 = Mr[0], r1 = Mr[1], r2 = Mr[2], r3 = Mr[3];
        float row[16] = {r0.x,r0.y,r0.z,r0.w, r1.x,r1.y,r1.z,r1.w,
                         r2.x,r2.y,r2.z,r2.w, r3.x,r3.y,r3.z,r3.w};
        float x[15];
#pragma unroll
        for (int k = 0; k < 15; k++)
            x[k] = row[k] + __shfl_sync(0xffffffffu, P, k, 16);
        P = lse15(x);
    }
    if (i < 15 && j < 15)
        g_M2[((size_t)g*15 + i)*16 + j] = P;
}

// ---------------- K5: serial combine + indiv + output -------------------------
__global__ void __launch_bounds__(256) k_final(const int* __restrict__ tags,
                                               const int* __restrict__ lens,
                                               float* __restrict__ out) {
    __shared__ float s_logZ;
    __shared__ float parts[256];
    int tid = threadIdx.x;

    if (tid < 32) {
        int i = tid & 15;
        int ic = min(i, 14);
        float v = (i == 0) ? 0.0f : NEG;
#pragma unroll
        for (int g = 0; g < GRP_; g++) {
            const float4* Mr = (const float4*)(g_M2 + ((size_t)g*15 + ic)*16);
            float4 r0 = Mr[0], r1 = Mr[1], r2 = Mr[2], r3 = Mr[3];
            float row[16] = {r0.x,r0.y,r0.z,r0.w, r1.x,r1.y,r1.z,r1.w,
                             r2.x,r2.y,r2.z,r2.w, r3.x,r3.y,r3.z,r3.w};
            float x[15];
#pragma unroll
            for (int k = 0; k < 15; k++)
                x[k] = row[k] + __shfl_sync(0xffffffffu, v, k, 16);
            v = lse15(x);
        }
        if (tid == 0) s_logZ = v;
    }
    float part = 0.0f;
    for (int s = tid; s < S_; s += 256) {
        int l = lens[s];
        if (l < 15) part += g_gtab[(l-1)*15 + tags[s]];
    }
    parts[tid] = part;
    __syncthreads();
    if (tid == 0) {
        float ind = 0.0f;
        for (int i = 0; i < 256; i++) ind += parts[i];
        out[0] = s_logZ - ind;
    }
}

// ---------------- launch ------------------------------------------------------
extern "C" void kernel_launch(void* const* d_in, const int* in_sizes, int n_in,
                              void* d_out, int out_size) {
    const float* data   = (const float*)d_in[0];
    const float* fWih   = (const float*)d_in[1];
    const float* fWhh   = (const float*)d_in[2];
    const float* fbih   = (const float*)d_in[3];
    const float* fbhh   = (const float*)d_in[4];
    const float* bWih   = (const float*)d_in[5];
    const float* bWhh   = (const float*)d_in[6];
    const float* bbih   = (const float*)d_in[7];
    const float* bbhh   = (const float*)d_in[8];
    const float* fh0    = (const float*)d_in[9];
    const float* fc0    = (const float*)d_in[10];
    const float* bh0    = (const float*)d_in[11];
    const float* bc0    = (const float*)d_in[12];
    const float* Yenc   = (const float*)d_in[13];
    const float* Zenc   = (const float*)d_in[14];
    const float* VW     = (const float*)d_in[15];
    const float* Vb     = (const float*)d_in[16];
    const float* WW     = (const float*)d_in[17];
    const float* Wb     = (const float*)d_in[18];
    const int*   tags   = (const int*)d_in[19];
    const int*   lens   = (const int*)d_in[20];
    float* out = (float*)d_out;

    k_proj<<<dim3(N_/128, 2), 128>>>(data, fWih, bWih, fbih, fbhh, bbih, bbhh);
    k_lstm<<<dim3(N_/16, 2), 256>>>(fWhh, bWhh, fh0, fc0, bh0, bc0);
    k_scores<<<N_/16, dim3(16, 16)>>>(Yenc, Zenc, VW, Vb, WW, Wb);
    k_dp1<<<SEG_/16, 256>>>();
    k_dp2<<<GRP_, 256>>>();
    k_final<<<1, 256>>>(tags, lens, out);
}

// round 5
// speedup vs baseline: 1.6352x; 1.0316x over previous
#include <cuda_runtime.h>
#include <math.h>

#define N_   16384
#define L_   15
#define K_   64
#define H_   16
#define NY_  15
#define S_   2048
#define NEG  (-1e30f)
#define SEG_ 512          // number of DP segments
#define SEGLEN_ (N_/SEG_) // 32
#define GRP_ 32           // groups after dp2
#define PERG_ (SEG_/GRP_) // 16

typedef unsigned long long u64;

// ---------------- scratch (device globals; no allocation allowed) ------------
__device__ float g_proj[2][(size_t)N_*64];   // permuted input projections
__device__ float g_h[2][(size_t)L_*N_*H_];   // fwd/bwd hidden states [l][n][h]
__device__ float g_A[N_*16];                 // A[p][d], stride 16 (d=15 unused)
__device__ float g_gtab[15*15];              // scores[p][p][y] for p<15
__device__ float g_M[SEG_*15*16];            // per-segment transfer rows [seg][i][j]
__device__ float g_M2[GRP_*15*16];           // combined matrices

// ---------------- fast math helpers -----------------------------------------
__device__ __forceinline__ float tanh_ap(float x) {
    float y; asm("tanh.approx.f32 %0, %1;" : "=f"(y) : "f"(x)); return y;
}
__device__ __forceinline__ float sigm(float x) {
    return fmaf(tanh_ap(0.5f*x), 0.5f, 0.5f);
}
__device__ __forceinline__ u64 pk2(float lo, float hi) {
    u64 r; asm("mov.b64 %0, {%1,%2};" : "=l"(r) : "f"(lo), "f"(hi)); return r;
}
__device__ __forceinline__ u64 fma2(u64 a, u64 b, u64 c) {
    u64 d; asm("fma.rn.f32x2 %0, %1, %2, %3;" : "=l"(d) : "l"(a), "l"(b), "l"(c)); return d;
}
__device__ __forceinline__ float2 upk2(u64 a) {
    float lo, hi; asm("mov.b64 {%0,%1}, %2;" : "=f"(lo), "=f"(hi) : "l"(a));
    float2 v; v.x = lo; v.y = hi; return v;
}
__device__ __forceinline__ float max15(const float x[15]) {
    float a = fmaxf(x[0],x[1]),  b = fmaxf(x[2],x[3]);
    float c = fmaxf(x[4],x[5]),  d = fmaxf(x[6],x[7]);
    float e = fmaxf(x[8],x[9]),  f = fmaxf(x[10],x[11]);
    float g = fmaxf(x[12],x[13]);
    a = fmaxf(a,b); c = fmaxf(c,d); e = fmaxf(e,f); g = fmaxf(g,x[14]);
    a = fmaxf(a,c); e = fmaxf(e,g);
    return fmaxf(a,e);
}
__device__ __forceinline__ float lse15(const float x[15]) {
    float m = max15(x);
    float s0 = __expf(x[0]-m)  + __expf(x[1]-m);
    float s1 = __expf(x[2]-m)  + __expf(x[3]-m);
    float s2 = __expf(x[4]-m)  + __expf(x[5]-m);
    float s3 = __expf(x[6]-m)  + __expf(x[7]-m);
    float s4 = __expf(x[8]-m)  + __expf(x[9]-m);
    float s5 = __expf(x[10]-m) + __expf(x[11]-m);
    float s6 = __expf(x[12]-m) + __expf(x[13]-m);
    float s7 = __expf(x[14]-m);
    s0 += s1; s2 += s3; s4 += s5; s6 += s7;
    s0 += s2; s4 += s6;
    return m + __logf(s0 + s4);
}

// ---------------- K1: input projection (2 small GEMMs) -----------------------
__global__ void __launch_bounds__(128) k_proj(const float* __restrict__ data,
                                              const float* __restrict__ fWih,
                                              const float* __restrict__ bWih,
                                              const float* __restrict__ fbih,
                                              const float* __restrict__ fbhh,
                                              const float* __restrict__ bbih,
                                              const float* __restrict__ bbhh) {
    const int dir = blockIdx.y;
    const float* Wih = dir ? bWih : fWih;
    const float* bih = dir ? bbih : fbih;
    const float* bhh = dir ? bbhh : fbhh;
    __shared__ __align__(16) float WTs[4096];
    __shared__ float bs[64];
    // transposed, gate-permuted Wih: WTs[k*64 + (j*4+c)] = Wih[(c*16+j)*64 + k]
    for (int i = threadIdx.x; i < 4096; i += 128) {
        int k = i >> 6, m = i & 63, j = m >> 2, c = m & 3, r = c*16 + j;
        WTs[i] = Wih[r*64 + k];
    }
    if (threadIdx.x < 64) {
        int j = threadIdx.x >> 2, c = threadIdx.x & 3, r = c*16 + j;
        bs[threadIdx.x] = bih[r] + bhh[r];
    }
    __syncthreads();

    int n = blockIdx.x * 128 + threadIdx.x;
    float d[64];
    const float4* dp = (const float4*)(data + (size_t)n * 64);
#pragma unroll
    for (int i = 0; i < 16; i++) {
        float4 v = dp[i];
        d[i*4+0] = v.x; d[i*4+1] = v.y; d[i*4+2] = v.z; d[i*4+3] = v.w;
    }
    float4* outp = (float4*)(g_proj[dir] + (size_t)n * 64);
    const float4* W4 = (const float4*)WTs;
    for (int mf = 0; mf < 16; mf++) {
        float4 acc = make_float4(bs[mf*4+0], bs[mf*4+1], bs[mf*4+2], bs[mf*4+3]);
#pragma unroll
        for (int k = 0; k < 64; k++) {
            float4 w = W4[k*16 + mf];
            acc.x += d[k]*w.x; acc.y += d[k]*w.y; acc.z += d[k]*w.z; acc.w += d[k]*w.w;
        }
        outp[mf] = acc;
    }
}

// ---------------- K2: 32768 independent 15-step LSTMs -------------------------
// 16 lanes per run (lane j owns hidden unit j), 2 runs per warp.
__global__ void __launch_bounds__(256) k_lstm(const float* __restrict__ fWhh,
                                              const float* __restrict__ bWhh,
                                              const float* __restrict__ fh0,
                                              const float* __restrict__ fc0,
                                              const float* __restrict__ bh0,
                                              const float* __restrict__ bc0) {
    const int dir = blockIdx.y;
    __shared__ __align__(16) float Ws[1024];
    __shared__ float h0s[16], c0s[16];
    const float* Whh = dir ? bWhh : fWhh;
    for (int i = threadIdx.x; i < 1024; i += 256) Ws[i] = Whh[i];
    if (threadIdx.x < 16) {
        h0s[threadIdx.x] = dir ? bh0[threadIdx.x] : fh0[threadIdx.x];
        c0s[threadIdx.x] = dir ? bc0[threadIdx.x] : fc0[threadIdx.x];
    }
    __syncthreads();

    int lane = threadIdx.x & 31;
    int j = lane & 15;
    int gw = blockIdx.x * 8 + (threadIdx.x >> 5);
    int n = gw * 2 + (lane >> 4);

    u64 wi2[8], wf2[8], wg2[8], wo2[8];
#pragma unroll
    for (int k = 0; k < 8; k++) {
        wi2[k] = *(const u64*)&Ws[(0  + j)*16 + 2*k];
        wf2[k] = *(const u64*)&Ws[(16 + j)*16 + 2*k];
        wg2[k] = *(const u64*)&Ws[(32 + j)*16 + 2*k];
        wo2[k] = *(const u64*)&Ws[(48 + j)*16 + 2*k];
    }
    float h[16];
#pragma unroll
    for (int k = 0; k < 16; k++) h[k] = h0s[k];
    float c = c0s[j];

    const float* proj = g_proj[dir];
    float* out = g_h[dir];

    for (int l = 0; l < 15; l++) {
        int idx = dir ? max(n - l, 0) : min(n + l, N_ - 1);
        float4 p4 = *(const float4*)(proj + (size_t)idx * 64 + j * 4);
        u64 h2[8];
#pragma unroll
        for (int k = 0; k < 8; k++) h2[k] = pk2(h[2*k], h[2*k+1]);
        u64 ai2 = pk2(p4.x, 0.f), af2 = pk2(p4.y, 0.f);
        u64 ag2 = pk2(p4.z, 0.f), ao2 = pk2(p4.w, 0.f);
#pragma unroll
        for (int k = 0; k < 8; k++) {
            ai2 = fma2(h2[k], wi2[k], ai2);
            af2 = fma2(h2[k], wf2[k], af2);
            ag2 = fma2(h2[k], wg2[k], ag2);
            ao2 = fma2(h2[k], wo2[k], ao2);
        }
        float2 vi = upk2(ai2), vf = upk2(af2), vg = upk2(ag2), vo = upk2(ao2);
        float ai = vi.x + vi.y, af = vf.x + vf.y;
        float ag = vg.x + vg.y, ao = vo.x + vo.y;
        float tg = tanh_ap(ag);
        c = sigm(af)*c + sigm(ai)*tg;
        float hj = sigm(ao)*tanh_ap(c);
        out[((size_t)l*N_ + n)*16 + j] = hj;
#pragma unroll
        for (int k = 0; k < 16; k++) h[k] = __shfl_sync(0xffffffffu, hj, k, 16);
    }
}

// ---------------- K3: scores + logsumexp over y -> A[p][d] --------------------
__global__ void __launch_bounds__(256) k_scores(const float* __restrict__ Yenc,
                                                const float* __restrict__ Zenc,
                                                const float* __restrict__ VW,
                                                const float* __restrict__ Vb,
                                                const float* __restrict__ WW,
                                                const float* __restrict__ Wb) {
    __shared__ __align__(16) float V1S[512];   // [h][32]
    __shared__ __align__(8)  float ypS[240];   // [y][16]
    __shared__ __align__(8)  float zbS[240];   // [d][16]
    __shared__ float Wsh[16];
    __shared__ float Wbs;
    int t = threadIdx.y * 16 + threadIdx.x;
    for (int i = t; i < 512; i += 256) {
        int h = i >> 5, k = i & 31;
        V1S[i] = VW[h*68 + k];
    }
    if (t < 240) {
        int y = t >> 4, h = t & 15;
        float s = 0.0f;
        for (int u = 0; u < 32; u++) s += Yenc[y*32 + u] * VW[h*68 + 32 + u];
        ypS[t] = s;
        float z = Vb[h];
        for (int u = 0; u < 4; u++) z += Zenc[y*4 + u] * VW[h*68 + 64 + u];
        zbS[t] = z;
    }
    if (t < 16)  Wsh[t] = WW[t];
    if (t == 0)  Wbs = Wb[0];
    __syncthreads();

    int d = threadIdx.x;
    int p = blockIdx.x * 16 + threadIdx.y;
    if (d >= 15) return;
    int pm = max(p - d, 0);

    u64 fg2[8], bw2[8];
    const ulonglong2* f4 = (const ulonglong2*)(g_h[0] + ((size_t)d*N_ + pm)*16);
    const ulonglong2* b4 = (const ulonglong2*)(g_h[1] + ((size_t)d*N_ + p )*16);
#pragma unroll
    for (int i = 0; i < 4; i++) {
        ulonglong2 v = f4[i]; fg2[2*i] = v.x; fg2[2*i+1] = v.y;
        ulonglong2 u = b4[i]; bw2[2*i] = u.x; bw2[2*i+1] = u.y;
    }
    float bse[16];
#pragma unroll
    for (int h = 0; h < 16; h++) {
        u64 acc = pk2(zbS[d*16 + h], 0.0f);
#pragma unroll
        for (int k = 0; k < 8; k++)
            acc = fma2(fg2[k], *(const u64*)&V1S[h*32 + 2*k], acc);
#pragma unroll
        for (int k = 0; k < 8; k++)
            acc = fma2(bw2[k], *(const u64*)&V1S[h*32 + 16 + 2*k], acc);
        float2 a = upk2(acc);
        bse[h] = a.x + a.y;
    }
    float sarr[15];
#pragma unroll
    for (int y = 0; y < 15; y++) {
        float s = Wbs;
#pragma unroll
        for (int h = 0; h < 16; h++)
            s = fmaf(Wsh[h], tanh_ap(bse[h] + ypS[y*16 + h]), s);
        sarr[y] = s;
    }
    float A = lse15(sarr);
    if (d > p) A = NEG;
    g_A[p*16 + d] = A;
    if (p < 15 && d == p) {
#pragma unroll
        for (int y = 0; y < 15; y++) g_gtab[p*15 + y] = sarr[y];
    }
}

// ---------------- K4a: per-segment DP transfer matrices ----------------------
// lane j owns column j. buf is a circular ring of incoming-hist coefficients:
// ring[k] == buf[(hp_t + k) % 15], hp_t = (-t) mod 15. Fully unrolled so all
// indices are compile-time constants (no register shifting).
__global__ void __launch_bounds__(64) k_dp1() {
    int lane = threadIdx.x & 31;
    int j = lane & 15;
    int seg = (blockIdx.x * 2 + (threadIdx.x >> 5)) * 2 + (lane >> 4);

    float buf[15];
#pragma unroll
    for (int k = 0; k < 15; k++) buf[k] = (j == k) ? 0.0f : NEG;

    const float4* Ar = (const float4*)(g_A + (size_t)seg * SEGLEN_ * 16);
#pragma unroll
    for (int t = 0; t < SEGLEN_; t++) {
        const int hp = (15 - (t % 15)) % 15;        // compile-time
        float4 q0 = Ar[t*4+0], q1 = Ar[t*4+1], q2 = Ar[t*4+2], q3 = Ar[t*4+3];
        float row[16] = {q0.x,q0.y,q0.z,q0.w, q1.x,q1.y,q1.z,q1.w,
                         q2.x,q2.y,q2.z,q2.w, q3.x,q3.y,q3.z,q3.w};
        float x[15];
#pragma unroll
        for (int k = 0; k < 15; k++) x[k] = row[k] + buf[(hp + k) % 15];
        float nw = lse15(x);
        buf[(hp + 14) % 15] = nw;                    // new ring[0]
    }
    // final hp after 32 steps: (15 - 32%15)%15 = 13
    if (j < 15) {
#pragma unroll
        for (int i = 0; i < 15; i++)
            g_M[((size_t)seg*15 + i)*16 + j] = buf[(13 + i) % 15];
    }
}

// ---------------- K4b: parallel 16:1 matrix combine ---------------------------
// block g combines matrices [16g .. 16g+15] into g_M2[g].
// lane i (0..15 within half-warp) holds P[i][j] for column j = warp*2+half.
__global__ void __launch_bounds__(256) k_dp2() {
    int lane = threadIdx.x & 31;
    int i = lane & 15;
    int ic = min(i, 14);
    int j = (threadIdx.x >> 5) * 2 + (lane >> 4);   // 0..15
    int g = blockIdx.x;
    int m0 = g * PERG_;

    float P = g_M[((size_t)m0*15 + ic)*16 + j];
#pragma unroll
    for (int tt = 1; tt < PERG_; tt++) {
        const float4* Mr = (const float4*)(g_M + ((size_t)(m0+tt)*15 + ic)*16);
        float4 r0 = Mr[0], r1 = Mr[1], r2 = Mr[2], r3 = Mr[3];
        float row[16] = {r0.x,r0.y,r0.z,r0.w, r1.x,r1.y,r1.z,r1.w,
                         r2.x,r2.y,r2.z,r2.w, r3.x,r3.y,r3.z,r3.w};
        float x[15];
#pragma unroll
        for (int k = 0; k < 15; k++)
            x[k] = row[k] + __shfl_sync(0xffffffffu, P, k, 16);
        P = lse15(x);
    }
    if (i < 15 && j < 15)
        g_M2[((size_t)g*15 + i)*16 + j] = P;
}

// ---------------- K5: serial combine + indiv + output -------------------------
__global__ void __launch_bounds__(256) k_final(const int* __restrict__ tags,
                                               const int* __restrict__ lens,
                                               float* __restrict__ out) {
    __shared__ float s_logZ;
    __shared__ float parts[256];
    int tid = threadIdx.x;

    if (tid < 32) {
        int i = tid & 15;
        int ic = min(i, 14);
        float v = (i == 0) ? 0.0f : NEG;
#pragma unroll 4
        for (int g = 0; g < GRP_; g++) {
            const float4* Mr = (const float4*)(g_M2 + ((size_t)g*15 + ic)*16);
            float4 r0 = Mr[0], r1 = Mr[1], r2 = Mr[2], r3 = Mr[3];
            float row[16] = {r0.x,r0.y,r0.z,r0.w, r1.x,r1.y,r1.z,r1.w,
                             r2.x,r2.y,r2.z,r2.w, r3.x,r3.y,r3.z,r3.w};
            float x[15];
#pragma unroll
            for (int k = 0; k < 15; k++)
                x[k] = row[k] + __shfl_sync(0xffffffffu, v, k, 16);
            v = lse15(x);
        }
        if (tid == 0) s_logZ = v;
    }
    float part = 0.0f;
    for (int s = tid; s < S_; s += 256) {
        int l = lens[s];
        if (l < 15) part += g_gtab[(l-1)*15 + tags[s]];
    }
    parts[tid] = part;
    __syncthreads();
    if (tid == 0) {
        float ind = 0.0f;
        for (int i = 0; i < 256; i++) ind += parts[i];
        out[0] = s_logZ - ind;
    }
}

// ---------------- launch ------------------------------------------------------
extern "C" void kernel_launch(void* const* d_in, const int* in_sizes, int n_in,
                              void* d_out, int out_size) {
    const float* data   = (const float*)d_in[0];
    const float* fWih   = (const float*)d_in[1];
    const float* fWhh   = (const float*)d_in[2];
    const float* fbih   = (const float*)d_in[3];
    const float* fbhh   = (const float*)d_in[4];
    const float* bWih   = (const float*)d_in[5];
    const float* bWhh   = (const float*)d_in[6];
    const float* bbih   = (const float*)d_in[7];
    const float* bbhh   = (const float*)d_in[8];
    const float* fh0    = (const float*)d_in[9];
    const float* fc0    = (const float*)d_in[10];
    const float* bh0    = (const float*)d_in[11];
    const float* bc0    = (const float*)d_in[12];
    const float* Yenc   = (const float*)d_in[13];
    const float* Zenc   = (const float*)d_in[14];
    const float* VW     = (const float*)d_in[15];
    const float* Vb     = (const float*)d_in[16];
    const float* WW     = (const float*)d_in[17];
    const float* Wb     = (const float*)d_in[18];
    const int*   tags   = (const int*)d_in[19];
    const int*   lens   = (const int*)d_in[20];
    float* out = (float*)d_out;

    k_proj<<<dim3(N_/128, 2), 128>>>(data, fWih, bWih, fbih, fbhh, bbih, bbhh);
    k_lstm<<<dim3(N_/16, 2), 256>>>(fWhh, bWhh, fh0, fc0, bh0, bc0);
    k_scores<<<N_/16, dim3(16, 16)>>>(Yenc, Zenc, VW, Vb, WW, Wb);
    k_dp1<<<SEG_/4, 64>>>();
    k_dp2<<<GRP_, 256>>>();
    k_final<<<1, 256>>>(tags, lens, out);
}

// round 6
// speedup vs baseline: 1.7106x; 1.0462x over previous
#include <cuda_runtime.h>
#include <math.h>

#define N_   16384
#define L_   15
#define K_   64
#define H_   16
#define NY_  15
#define S_   2048
#define NEG  (-1e30f)
#define SEG_ 2048         // number of DP segments
#define SEGLEN_ (N_/SEG_) // 8
#define G2_  (SEG_/16)    // 128 after dp2
#define G3_  (G2_/16)     // 8 after dp3

typedef unsigned long long u64;

// ---------------- scratch (device globals; no allocation allowed) ------------
__device__ float g_proj[2][(size_t)N_*64];   // permuted input projections
__device__ float g_h[2][(size_t)L_*N_*H_];   // fwd/bwd hidden states [l][n][h]
__device__ float g_A[N_*16];                 // A[p][d], stride 16 (d=15 unused)
__device__ float g_gtab[15*15];              // scores[p][p][y] for p<15
__device__ float g_M[(size_t)SEG_*15*16];    // per-segment transfer rows [seg][i][j]
__device__ float g_M2[G2_*15*16];            // level-2 combined matrices
__device__ float g_M3[G3_*15*16];            // level-3 combined matrices

// ---------------- fast math helpers -----------------------------------------
__device__ __forceinline__ float tanh_ap(float x) {
    float y; asm("tanh.approx.f32 %0, %1;" : "=f"(y) : "f"(x)); return y;
}
__device__ __forceinline__ float sigm(float x) {
    return fmaf(tanh_ap(0.5f*x), 0.5f, 0.5f);
}
__device__ __forceinline__ u64 pk2(float lo, float hi) {
    u64 r; asm("mov.b64 %0, {%1,%2};" : "=l"(r) : "f"(lo), "f"(hi)); return r;
}
__device__ __forceinline__ u64 fma2(u64 a, u64 b, u64 c) {
    u64 d; asm("fma.rn.f32x2 %0, %1, %2, %3;" : "=l"(d) : "l"(a), "l"(b), "l"(c)); return d;
}
__device__ __forceinline__ float2 upk2(u64 a) {
    float lo, hi; asm("mov.b64 {%0,%1}, %2;" : "=f"(lo), "=f"(hi) : "l"(a));
    float2 v; v.x = lo; v.y = hi; return v;
}
__device__ __forceinline__ float max15(const float x[15]) {
    float a = fmaxf(x[0],x[1]),  b = fmaxf(x[2],x[3]);
    float c = fmaxf(x[4],x[5]),  d = fmaxf(x[6],x[7]);
    float e = fmaxf(x[8],x[9]),  f = fmaxf(x[10],x[11]);
    float g = fmaxf(x[12],x[13]);
    a = fmaxf(a,b); c = fmaxf(c,d); e = fmaxf(e,f); g = fmaxf(g,x[14]);
    a = fmaxf(a,c); e = fmaxf(e,g);
    return fmaxf(a,e);
}
__device__ __forceinline__ float lse15(const float x[15]) {
    float m = max15(x);
    float s0 = __expf(x[0]-m)  + __expf(x[1]-m);
    float s1 = __expf(x[2]-m)  + __expf(x[3]-m);
    float s2 = __expf(x[4]-m)  + __expf(x[5]-m);
    float s3 = __expf(x[6]-m)  + __expf(x[7]-m);
    float s4 = __expf(x[8]-m)  + __expf(x[9]-m);
    float s5 = __expf(x[10]-m) + __expf(x[11]-m);
    float s6 = __expf(x[12]-m) + __expf(x[13]-m);
    float s7 = __expf(x[14]-m);
    s0 += s1; s2 += s3; s4 += s5; s6 += s7;
    s0 += s2; s4 += s6;
    return m + __logf(s0 + s4);
}

// ---------------- K1: input projection (2 small GEMMs) -----------------------
__global__ void __launch_bounds__(128) k_proj(const float* __restrict__ data,
                                              const float* __restrict__ fWih,
                                              const float* __restrict__ bWih,
                                              const float* __restrict__ fbih,
                                              const float* __restrict__ fbhh,
                                              const float* __restrict__ bbih,
                                              const float* __restrict__ bbhh) {
    const int dir = blockIdx.y;
    const float* Wih = dir ? bWih : fWih;
    const float* bih = dir ? bbih : fbih;
    const float* bhh = dir ? bbhh : fbhh;
    __shared__ __align__(16) float WTs[4096];
    __shared__ float bs[64];
    // transposed, gate-permuted Wih: WTs[k*64 + (j*4+c)] = Wih[(c*16+j)*64 + k]
    for (int i = threadIdx.x; i < 4096; i += 128) {
        int k = i >> 6, m = i & 63, j = m >> 2, c = m & 3, r = c*16 + j;
        WTs[i] = Wih[r*64 + k];
    }
    if (threadIdx.x < 64) {
        int j = threadIdx.x >> 2, c = threadIdx.x & 3, r = c*16 + j;
        bs[threadIdx.x] = bih[r] + bhh[r];
    }
    __syncthreads();

    int n = blockIdx.x * 128 + threadIdx.x;
    float d[64];
    const float4* dp = (const float4*)(data + (size_t)n * 64);
#pragma unroll
    for (int i = 0; i < 16; i++) {
        float4 v = dp[i];
        d[i*4+0] = v.x; d[i*4+1] = v.y; d[i*4+2] = v.z; d[i*4+3] = v.w;
    }
    float4* outp = (float4*)(g_proj[dir] + (size_t)n * 64);
    const float4* W4 = (const float4*)WTs;
    for (int mf = 0; mf < 16; mf++) {
        float4 acc = make_float4(bs[mf*4+0], bs[mf*4+1], bs[mf*4+2], bs[mf*4+3]);
#pragma unroll
        for (int k = 0; k < 64; k++) {
            float4 w = W4[k*16 + mf];
            acc.x += d[k]*w.x; acc.y += d[k]*w.y; acc.z += d[k]*w.z; acc.w += d[k]*w.w;
        }
        outp[mf] = acc;
    }
}

// ---------------- K2: 32768 independent 15-step LSTMs -------------------------
// 16 lanes per run (lane j owns hidden unit j), 2 runs per warp.
__global__ void __launch_bounds__(256) k_lstm(const float* __restrict__ fWhh,
                                              const float* __restrict__ bWhh,
                                              const float* __restrict__ fh0,
                                              const float* __restrict__ fc0,
                                              const float* __restrict__ bh0,
                                              const float* __restrict__ bc0) {
    const int dir = blockIdx.y;
    __shared__ __align__(16) float Ws[1024];
    __shared__ float h0s[16], c0s[16];
    const float* Whh = dir ? bWhh : fWhh;
    for (int i = threadIdx.x; i < 1024; i += 256) Ws[i] = Whh[i];
    if (threadIdx.x < 16) {
        h0s[threadIdx.x] = dir ? bh0[threadIdx.x] : fh0[threadIdx.x];
        c0s[threadIdx.x] = dir ? bc0[threadIdx.x] : fc0[threadIdx.x];
    }
    __syncthreads();

    int lane = threadIdx.x & 31;
    int j = lane & 15;
    int gw = blockIdx.x * 8 + (threadIdx.x >> 5);
    int n = gw * 2 + (lane >> 4);

    u64 wi2[8], wf2[8], wg2[8], wo2[8];
#pragma unroll
    for (int k = 0; k < 8; k++) {
        wi2[k] = *(const u64*)&Ws[(0  + j)*16 + 2*k];
        wf2[k] = *(const u64*)&Ws[(16 + j)*16 + 2*k];
        wg2[k] = *(const u64*)&Ws[(32 + j)*16 + 2*k];
        wo2[k] = *(const u64*)&Ws[(48 + j)*16 + 2*k];
    }
    float h[16];
#pragma unroll
    for (int k = 0; k < 16; k++) h[k] = h0s[k];
    float c = c0s[j];

    const float* proj = g_proj[dir];
    float* out = g_h[dir];

    for (int l = 0; l < 15; l++) {
        int idx = dir ? max(n - l, 0) : min(n + l, N_ - 1);
        float4 p4 = *(const float4*)(proj + (size_t)idx * 64 + j * 4);
        u64 h2[8];
#pragma unroll
        for (int k = 0; k < 8; k++) h2[k] = pk2(h[2*k], h[2*k+1]);
        u64 ai2 = pk2(p4.x, 0.f), af2 = pk2(p4.y, 0.f);
        u64 ag2 = pk2(p4.z, 0.f), ao2 = pk2(p4.w, 0.f);
#pragma unroll
        for (int k = 0; k < 8; k++) {
            ai2 = fma2(h2[k], wi2[k], ai2);
            af2 = fma2(h2[k], wf2[k], af2);
            ag2 = fma2(h2[k], wg2[k], ag2);
            ao2 = fma2(h2[k], wo2[k], ao2);
        }
        float2 vi = upk2(ai2), vf = upk2(af2), vg = upk2(ag2), vo = upk2(ao2);
        float ai = vi.x + vi.y, af = vf.x + vf.y;
        float ag = vg.x + vg.y, ao = vo.x + vo.y;
        float tg = tanh_ap(ag);
        c = sigm(af)*c + sigm(ai)*tg;
        float hj = sigm(ao)*tanh_ap(c);
        out[((size_t)l*N_ + n)*16 + j] = hj;
#pragma unroll
        for (int k = 0; k < 16; k++) h[k] = __shfl_sync(0xffffffffu, hj, k, 16);
    }
}

// ---------------- K3: scores + logsumexp over y -> A[p][d] --------------------
__global__ void __launch_bounds__(256) k_scores(const float* __restrict__ Yenc,
                                                const float* __restrict__ Zenc,
                                                const float* __restrict__ VW,
                                                const float* __restrict__ Vb,
                                                const float* __restrict__ WW,
                                                const float* __restrict__ Wb) {
    __shared__ __align__(16) float V1S[512];   // [h][32]
    __shared__ __align__(8)  float ypS[240];   // [y][16]
    __shared__ __align__(8)  float zbS[240];   // [d][16]
    __shared__ float Wsh[16];
    __shared__ float Wbs;
    int t = threadIdx.y * 16 + threadIdx.x;
    for (int i = t; i < 512; i += 256) {
        int h = i >> 5, k = i & 31;
        V1S[i] = VW[h*68 + k];
    }
    if (t < 240) {
        int y = t >> 4, h = t & 15;
        float s = 0.0f;
        for (int u = 0; u < 32; u++) s += Yenc[y*32 + u] * VW[h*68 + 32 + u];
        ypS[t] = s;
        float z = Vb[h];
        for (int u = 0; u < 4; u++) z += Zenc[y*4 + u] * VW[h*68 + 64 + u];
        zbS[t] = z;
    }
    if (t < 16)  Wsh[t] = WW[t];
    if (t == 0)  Wbs = Wb[0];
    __syncthreads();

    int d = threadIdx.x;
    int p = blockIdx.x * 16 + threadIdx.y;
    if (d >= 15) return;
    int pm = max(p - d, 0);

    u64 fg2[8], bw2[8];
    const ulonglong2* f4 = (const ulonglong2*)(g_h[0] + ((size_t)d*N_ + pm)*16);
    const ulonglong2* b4 = (const ulonglong2*)(g_h[1] + ((size_t)d*N_ + p )*16);
#pragma unroll
    for (int i = 0; i < 4; i++) {
        ulonglong2 v = f4[i]; fg2[2*i] = v.x; fg2[2*i+1] = v.y;
        ulonglong2 u = b4[i]; bw2[2*i] = u.x; bw2[2*i+1] = u.y;
    }
    float bse[16];
#pragma unroll
    for (int h = 0; h < 16; h++) {
        u64 acc = pk2(zbS[d*16 + h], 0.0f);
#pragma unroll
        for (int k = 0; k < 8; k++)
            acc = fma2(fg2[k], *(const u64*)&V1S[h*32 + 2*k], acc);
#pragma unroll
        for (int k = 0; k < 8; k++)
            acc = fma2(bw2[k], *(const u64*)&V1S[h*32 + 16 + 2*k], acc);
        float2 a = upk2(acc);
        bse[h] = a.x + a.y;
    }
    float sarr[15];
#pragma unroll
    for (int y = 0; y < 15; y++) {
        float s = Wbs;
#pragma unroll
        for (int h = 0; h < 16; h++)
            s = fmaf(Wsh[h], tanh_ap(bse[h] + ypS[y*16 + h]), s);
        sarr[y] = s;
    }
    float A = lse15(sarr);
    if (d > p) A = NEG;
    g_A[p*16 + d] = A;
    if (p < 15 && d == p) {
#pragma unroll
        for (int y = 0; y < 15; y++) g_gtab[p*15 + y] = sarr[y];
    }
}

// ---------------- K4a: per-segment DP transfer matrices ----------------------
// lane j owns column j. buf is a circular ring of incoming-hist coefficients:
// ring[k] == buf[(hp_t + k) % 15], hp_t = (-t) mod 15. Fully unrolled so all
// indices are compile-time constants. SEGLEN=8 -> final hp = 7.
__global__ void __launch_bounds__(256) k_dp1() {
    int lane = threadIdx.x & 31;
    int j = lane & 15;
    int seg = (blockIdx.x * 8 + (threadIdx.x >> 5)) * 2 + (lane >> 4);

    float buf[15];
#pragma unroll
    for (int k = 0; k < 15; k++) buf[k] = (j == k) ? 0.0f : NEG;

    const float4* Ar = (const float4*)(g_A + (size_t)seg * SEGLEN_ * 16);
#pragma unroll
    for (int t = 0; t < SEGLEN_; t++) {
        const int hp = (15 - (t % 15)) % 15;        // compile-time
        float4 q0 = Ar[t*4+0], q1 = Ar[t*4+1], q2 = Ar[t*4+2], q3 = Ar[t*4+3];
        float row[16] = {q0.x,q0.y,q0.z,q0.w, q1.x,q1.y,q1.z,q1.w,
                         q2.x,q2.y,q2.z,q2.w, q3.x,q3.y,q3.z,q3.w};
        float x[15];
#pragma unroll
        for (int k = 0; k < 15; k++) x[k] = row[k] + buf[(hp + k) % 15];
        float nw = lse15(x);
        buf[(hp + 14) % 15] = nw;                    // new ring[0]
    }
    const int HPF = (15 - (SEGLEN_ % 15)) % 15;      // 7 for SEGLEN=8
    if (j < 15) {
#pragma unroll
        for (int i = 0; i < 15; i++)
            g_M[((size_t)seg*15 + i)*16 + j] = buf[(HPF + i) % 15];
    }
}

// ---------------- generic 16:1 log-semiring matrix combine --------------------
// block g combines src matrices [16g .. 16g+15] into dst[g].
// lane i (0..15 within half-warp) holds P[i][j] for column j = warp*2+half.
__device__ __forceinline__ void combine16(const float* __restrict__ src,
                                          float* __restrict__ dst) {
    int lane = threadIdx.x & 31;
    int i = lane & 15;
    int ic = min(i, 14);
    int j = (threadIdx.x >> 5) * 2 + (lane >> 4);   // 0..15
    int g = blockIdx.x;
    int m0 = g * 16;

    float P = src[((size_t)m0*15 + ic)*16 + j];
#pragma unroll
    for (int tt = 1; tt < 16; tt++) {
        const float4* Mr = (const float4*)(src + ((size_t)(m0+tt)*15 + ic)*16);
        float4 r0 = Mr[0], r1 = Mr[1], r2 = Mr[2], r3 = Mr[3];
        float row[16] = {r0.x,r0.y,r0.z,r0.w, r1.x,r1.y,r1.z,r1.w,
                         r2.x,r2.y,r2.z,r2.w, r3.x,r3.y,r3.z,r3.w};
        float x[15];
#pragma unroll
        for (int k = 0; k < 15; k++)
            x[k] = row[k] + __shfl_sync(0xffffffffu, P, k, 16);
        P = lse15(x);
    }
    if (i < 15 && j < 15)
        dst[((size_t)g*15 + i)*16 + j] = P;
}

__global__ void __launch_bounds__(256) k_dp2() { combine16(g_M,  g_M2); }
__global__ void __launch_bounds__(256) k_dp3() { combine16(g_M2, g_M3); }

// ---------------- K5: fold 8 matrices + indiv + output ------------------------
__global__ void __launch_bounds__(256) k_final(const int* __restrict__ tags,
                                               const int* __restrict__ lens,
                                               float* __restrict__ out) {
    __shared__ float s_logZ;
    __shared__ float parts[256];
    int tid = threadIdx.x;

    if (tid < 32) {
        int i = tid & 15;
        int ic = min(i, 14);
        float v = (i == 0) ? 0.0f : NEG;
#pragma unroll
        for (int g = 0; g < G3_; g++) {
            const float4* Mr = (const float4*)(g_M3 + ((size_t)g*15 + ic)*16);
            float4 r0 = Mr[0], r1 = Mr[1], r2 = Mr[2], r3 = Mr[3];
            float row[16] = {r0.x,r0.y,r0.z,r0.w, r1.x,r1.y,r1.z,r1.w,
                             r2.x,r2.y,r2.z,r2.w, r3.x,r3.y,r3.z,r3.w};
            float x[15];
#pragma unroll
            for (int k = 0; k < 15; k++)
                x[k] = row[k] + __shfl_sync(0xffffffffu, v, k, 16);
            v = lse15(x);
        }
        if (tid == 0) s_logZ = v;
    }
    float part = 0.0f;
    for (int s = tid; s < S_; s += 256) {
        int l = lens[s];
        if (l < 15) part += g_gtab[(l-1)*15 + tags[s]];
    }
    parts[tid] = part;
    __syncthreads();
    if (tid == 0) {
        float ind = 0.0f;
        for (int i = 0; i < 256; i++) ind += parts[i];
        out[0] = s_logZ - ind;
    }
}

// ---------------- launch ------------------------------------------------------
extern "C" void kernel_launch(void* const* d_in, const int* in_sizes, int n_in,
                              void* d_out, int out_size) {
    const float* data   = (const float*)d_in[0];
    const float* fWih   = (const float*)d_in[1];
    const float* fWhh   = (const float*)d_in[2];
    const float* fbih   = (const float*)d_in[3];
    const float* fbhh   = (const float*)d_in[4];
    const float* bWih   = (const float*)d_in[5];
    const float* bWhh   = (const float*)d_in[6];
    const float* bbih   = (const float*)d_in[7];
    const float* bbhh   = (const float*)d_in[8];
    const float* fh0    = (const float*)d_in[9];
    const float* fc0    = (const float*)d_in[10];
    const float* bh0    = (const float*)d_in[11];
    const float* bc0    = (const float*)d_in[12];
    const float* Yenc   = (const float*)d_in[13];
    const float* Zenc   = (const float*)d_in[14];
    const float* VW     = (const float*)d_in[15];
    const float* Vb     = (const float*)d_in[16];
    const float* WW     = (const float*)d_in[17];
    const float* Wb     = (const float*)d_in[18];
    const int*   tags   = (const int*)d_in[19];
    const int*   lens   = (const int*)d_in[20];
    float* out = (float*)d_out;

    k_proj<<<dim3(N_/128, 2), 128>>>(data, fWih, bWih, fbih, fbhh, bbih, bbhh);
    k_lstm<<<dim3(N_/16, 2), 256>>>(fWhh, bWhh, fh0, fc0, bh0, bc0);
    k_scores<<<N_/16, dim3(16, 16)>>>(Yenc, Zenc, VW, Vb, WW, Wb);
    k_dp1<<<SEG_/16, 256>>>();
    k_dp2<<<G2_, 256>>>();
    k_dp3<<<G3_, 256>>>();
    k_final<<<1, 256>>>(tags, lens, out);
}